// round 3
// baseline (speedup 1.0000x reference)
#include <cuda_runtime.h>
#include <cuda_bf16.h>

// Problem constants (fixed by dataset)
#define NN   100000
#define NE   1600000
#define BG   256
#define DIN  128
#define HH   256
#define BN_EPS 1e-5f

// ---------------------------------------------------------------------------
// Scratch (device globals; referenced ONLY inside kernel bodies — taking the
// address of a __device__ symbol in host code yields a garbage host pointer)
// ---------------------------------------------------------------------------
__device__ float g_h[(size_t)NN * HH];    // GEMM output (h = A@W)
__device__ float g_agg[(size_t)NN * HH];  // scatter accumulator
__device__ float g_act[(size_t)NN * HH];  // activated layer output / residual
__device__ float g_deg[NN];
__device__ float g_dinv[NN];
__device__ float g_pool[BG * HH];
__device__ float g_cnt[BG];

// Vector reduction (no-return atomic add), sm_90+
__device__ __forceinline__ void red_add_v4(float* a, float4 v) {
    asm volatile("red.global.add.v4.f32 [%0], {%1,%2,%3,%4};"
                 :: "l"(a), "f"(v.x), "f"(v.y), "f"(v.z), "f"(v.w) : "memory");
}

// ---------------------------------------------------------------------------
// Init kernels
// ---------------------------------------------------------------------------
__global__ void k_zero_agg() {
    int i = blockIdx.x * blockDim.x + threadIdx.x;  // NN*HH/4 threads
    ((float4*)g_agg)[i] = make_float4(0.f, 0.f, 0.f, 0.f);
}

__global__ void k_init_small() {
    int i = blockIdx.x * blockDim.x + threadIdx.x;
    if (i < NN) g_deg[i] = 1.0f;          // self-loop weight
    if (i < BG * HH) g_pool[i] = 0.0f;
    if (i < BG) g_cnt[i] = 0.0f;
}

__global__ void k_deg(const int* __restrict__ dst, const float* __restrict__ ew) {
    int e = blockIdx.x * blockDim.x + threadIdx.x;
    if (e < NE) atomicAdd(&g_deg[dst[e]], ew[e]);
}

__global__ void k_cnt(const int* __restrict__ batch) {
    int n = blockIdx.x * blockDim.x + threadIdx.x;
    if (n < NN) atomicAdd(&g_cnt[batch[n]], 1.0f);
}

__global__ void k_dinv() {
    int n = blockIdx.x * blockDim.x + threadIdx.x;
    if (n < NN) g_dinv[n] = rsqrtf(g_deg[n]);
}

// ---------------------------------------------------------------------------
// SGEMM: g_h[M x 256] = A[M x K] @ B[K x 256]
// A = x (param) when USE_ACT=0, A = g_act (global) when USE_ACT=1.
// BM=128, BN=64, BK=16, 256 threads, 8x4 micro-tile per thread
// ---------------------------------------------------------------------------
template <int K, int USE_ACT>
__global__ __launch_bounds__(256) void k_sgemm(const float* __restrict__ Aparam,
                                               const float* __restrict__ Bm, int M) {
    const float* A = USE_ACT ? (const float*)g_act : Aparam;
    float* C = g_h;
    const int BM = 128, BN = 64, BK = 16;
    __shared__ float As[BK][BM + 4];   // padded rows; 528B row stride keeps 16B align
    __shared__ float Bs[BK][BN];

    int tid = threadIdx.x;
    int block_m = blockIdx.x * BM;
    int block_n = blockIdx.y * BN;
    int ty = tid / 16, tx = tid % 16;

    float acc[8][4];
#pragma unroll
    for (int i = 0; i < 8; i++)
#pragma unroll
        for (int j = 0; j < 4; j++) acc[i][j] = 0.f;

    for (int k0 = 0; k0 < K; k0 += BK) {
        // Load A tile (128 x 16) = 512 float4 -> 2 per thread, transposed to As[k][m]
#pragma unroll
        for (int it = 0; it < 2; it++) {
            int li = tid + it * 256;
            int m = li >> 2;          // 0..127
            int kq = li & 3;          // 0..3
            int gm = block_m + m;
            float4 v = make_float4(0.f, 0.f, 0.f, 0.f);
            if (gm < M) v = *(const float4*)(A + (size_t)gm * K + k0 + kq * 4);
            As[kq * 4 + 0][m] = v.x;
            As[kq * 4 + 1][m] = v.y;
            As[kq * 4 + 2][m] = v.z;
            As[kq * 4 + 3][m] = v.w;
        }
        // Load B tile (16 x 64) = 256 float4 -> 1 per thread
        {
            int k = tid / 16, nq = tid % 16;
            float4 v = *(const float4*)(Bm + (size_t)(k0 + k) * HH + block_n + nq * 4);
            *(float4*)&Bs[k][nq * 4] = v;
        }
        __syncthreads();
#pragma unroll
        for (int kk = 0; kk < BK; kk++) {
            float a[8], b[4];
            *(float4*)&a[0] = *(const float4*)&As[kk][ty * 8];
            *(float4*)&a[4] = *(const float4*)&As[kk][ty * 8 + 4];
            *(float4*)&b[0] = *(const float4*)&Bs[kk][tx * 4];
#pragma unroll
            for (int i = 0; i < 8; i++)
#pragma unroll
                for (int j = 0; j < 4; j++) acc[i][j] += a[i] * b[j];
        }
        __syncthreads();
    }
#pragma unroll
    for (int i = 0; i < 8; i++) {
        int gm = block_m + ty * 8 + i;
        if (gm < M) {
            float4 v = make_float4(acc[i][0], acc[i][1], acc[i][2], acc[i][3]);
            *(float4*)(C + (size_t)gm * HH + block_n + tx * 4) = v;
        }
    }
}

// ---------------------------------------------------------------------------
// Edge scatter: agg[dst] += h[src] * (dinv[src]*ew*dinv[dst])
// One warp per edge; 256 floats = 64 float4 -> 2 float4 per lane, v4 reductions.
// ---------------------------------------------------------------------------
__global__ __launch_bounds__(256) void k_scatter(const int* __restrict__ src,
                                                 const int* __restrict__ dst,
                                                 const float* __restrict__ ew) {
    int e = (blockIdx.x * blockDim.x + threadIdx.x) >> 5;
    if (e >= NE) return;
    int lane = threadIdx.x & 31;
    int s = __ldg(&src[e]);
    int d = __ldg(&dst[e]);
    float norm = __ldg(&g_dinv[s]) * __ldg(&ew[e]) * __ldg(&g_dinv[d]);
    const float4* hs = (const float4*)(g_h + (size_t)s * HH);
    float* ag = g_agg + (size_t)d * HH;
#pragma unroll
    for (int j = 0; j < 2; j++) {
        int idx = lane + j * 32;
        float4 v = __ldg(&hs[idx]);
        v.x *= norm; v.y *= norm; v.z *= norm; v.w *= norm;
        red_add_v4(ag + idx * 4, v);
    }
}

// ---------------------------------------------------------------------------
// Post layer 1: act = relu(bn(agg + h*dinv^2 + b)); also re-zero agg for layer 2
// ---------------------------------------------------------------------------
__global__ __launch_bounds__(256) void k_post1(const float* __restrict__ b1,
                                               const float* __restrict__ gm1,
                                               const float* __restrict__ be1,
                                               const float* __restrict__ rm1,
                                               const float* __restrict__ rv1) {
    int i = blockIdx.x * blockDim.x + threadIdx.x;  // over NN*HH/4
    int n = i >> 6;         // 64 float4 per row
    int c4 = i & 63;
    float di = g_dinv[n];
    float sc = di * di;
    float4 a = ((const float4*)g_agg)[i];
    float4 h = ((const float4*)g_h)[i];
    float4 bb = ((const float4*)b1)[c4];
    float4 g = ((const float4*)gm1)[c4];
    float4 be = ((const float4*)be1)[c4];
    float4 rm = ((const float4*)rm1)[c4];
    float4 rv = ((const float4*)rv1)[c4];
    float4 v;
    v.x = a.x + h.x * sc + bb.x;
    v.y = a.y + h.y * sc + bb.y;
    v.z = a.z + h.z * sc + bb.z;
    v.w = a.w + h.w * sc + bb.w;
    v.x = fmaxf((v.x - rm.x) * rsqrtf(rv.x + BN_EPS) * g.x + be.x, 0.f);
    v.y = fmaxf((v.y - rm.y) * rsqrtf(rv.y + BN_EPS) * g.y + be.y, 0.f);
    v.z = fmaxf((v.z - rm.z) * rsqrtf(rv.z + BN_EPS) * g.z + be.z, 0.f);
    v.w = fmaxf((v.w - rm.w) * rsqrtf(rv.w + BN_EPS) * g.w + be.w, 0.f);
    ((float4*)g_act)[i] = v;
    ((float4*)g_agg)[i] = make_float4(0.f, 0.f, 0.f, 0.f);
}

// ---------------------------------------------------------------------------
// Post layer 2: out = relu(bn(agg + h*dinv^2 + b)) + residual(act);
// store to act and accumulate into per-graph pool.
// ---------------------------------------------------------------------------
__global__ __launch_bounds__(256) void k_post2(const float* __restrict__ b2,
                                               const float* __restrict__ gm2,
                                               const float* __restrict__ be2,
                                               const float* __restrict__ rm2,
                                               const float* __restrict__ rv2,
                                               const int* __restrict__ batch) {
    int i = blockIdx.x * blockDim.x + threadIdx.x;
    int n = i >> 6;
    int c4 = i & 63;
    float di = g_dinv[n];
    float sc = di * di;
    float4 a = ((const float4*)g_agg)[i];
    float4 h = ((const float4*)g_h)[i];
    float4 bb = ((const float4*)b2)[c4];
    float4 g = ((const float4*)gm2)[c4];
    float4 be = ((const float4*)be2)[c4];
    float4 rm = ((const float4*)rm2)[c4];
    float4 rv = ((const float4*)rv2)[c4];
    float4 res = ((const float4*)g_act)[i];
    float4 v;
    v.x = a.x + h.x * sc + bb.x;
    v.y = a.y + h.y * sc + bb.y;
    v.z = a.z + h.z * sc + bb.z;
    v.w = a.w + h.w * sc + bb.w;
    v.x = fmaxf((v.x - rm.x) * rsqrtf(rv.x + BN_EPS) * g.x + be.x, 0.f) + res.x;
    v.y = fmaxf((v.y - rm.y) * rsqrtf(rv.y + BN_EPS) * g.y + be.y, 0.f) + res.y;
    v.z = fmaxf((v.z - rm.z) * rsqrtf(rv.z + BN_EPS) * g.z + be.z, 0.f) + res.z;
    v.w = fmaxf((v.w - rm.w) * rsqrtf(rv.w + BN_EPS) * g.w + be.w, 0.f) + res.w;
    ((float4*)g_act)[i] = v;
    int b = __ldg(&batch[n]);
    red_add_v4(&g_pool[b * HH + c4 * 4], v);
}

// ---------------------------------------------------------------------------
// Classifier head: one block per graph, 256 threads.
// ---------------------------------------------------------------------------
__global__ __launch_bounds__(256) void k_classifier(
    const float* __restrict__ cW1, const float* __restrict__ cb1,
    const float* __restrict__ cg1, const float* __restrict__ cbe1,
    const float* __restrict__ crm1, const float* __restrict__ crv1,
    const float* __restrict__ cW2, const float* __restrict__ cb2,
    const float* __restrict__ cg2, const float* __restrict__ cbe2,
    const float* __restrict__ crm2, const float* __restrict__ crv2,
    const float* __restrict__ cW3, const float* __restrict__ cb3,
    float* __restrict__ out, int out_size) {
    __shared__ float e[256];
    __shared__ float z1[256];
    __shared__ float z2[128];
    int g = blockIdx.x, t = threadIdx.x;
    float inv = 1.0f / fmaxf(g_cnt[g], 1.0f);
    e[t] = g_pool[g * HH + t] * inv;
    __syncthreads();
    // layer 1: 256 -> 256
    {
        float acc = cb1[t];
#pragma unroll 8
        for (int k = 0; k < 256; k++) acc += e[k] * cW1[k * 256 + t];
        acc = (acc - crm1[t]) * rsqrtf(crv1[t] + BN_EPS) * cg1[t] + cbe1[t];
        z1[t] = fmaxf(acc, 0.f);
    }
    __syncthreads();
    // layer 2: 256 -> 128
    if (t < 128) {
        float acc = cb2[t];
#pragma unroll 8
        for (int k = 0; k < 256; k++) acc += z1[k] * cW2[k * 128 + t];
        acc = (acc - crm2[t]) * rsqrtf(crv2[t] + BN_EPS) * cg2[t] + cbe2[t];
        z2[t] = fmaxf(acc, 0.f);
    }
    __syncthreads();
    // logits: 128 -> 2
    float logit = 0.f;
    if (t < 2) {
        logit = cb3[t];
#pragma unroll 8
        for (int k = 0; k < 128; k++) logit += z2[k] * cW3[k * 2 + t];
    }
    // output layout: logits [256*2] then emb [256*256]
    if (out_size >= 512 + BG * HH) {
        if (t < 2) out[g * 2 + t] = logit;
        out[512 + g * 256 + t] = e[t];
    } else if (out_size == BG * HH) {
        out[g * 256 + t] = e[t];
    } else {
        if (t < 2 && g * 2 + t < out_size) out[g * 2 + t] = logit;
    }
}

// ---------------------------------------------------------------------------
// Launch
// ---------------------------------------------------------------------------
extern "C" void kernel_launch(void* const* d_in, const int* in_sizes, int n_in,
                              void* d_out, int out_size) {
    const float* x    = (const float*)d_in[0];
    const int*   eidx = (const int*)d_in[1];
    const float* ew   = (const float*)d_in[2];
    const int*   batch= (const int*)d_in[3];
    const float* W1   = (const float*)d_in[4];
    const float* b1   = (const float*)d_in[5];
    const float* g1   = (const float*)d_in[6];
    const float* be1  = (const float*)d_in[7];
    const float* rm1  = (const float*)d_in[8];
    const float* rv1  = (const float*)d_in[9];
    const float* W2   = (const float*)d_in[10];
    const float* b2   = (const float*)d_in[11];
    const float* g2   = (const float*)d_in[12];
    const float* be2  = (const float*)d_in[13];
    const float* rm2  = (const float*)d_in[14];
    const float* rv2  = (const float*)d_in[15];
    const float* cW1  = (const float*)d_in[16];
    const float* cb1  = (const float*)d_in[17];
    const float* cg1  = (const float*)d_in[18];
    const float* cbe1 = (const float*)d_in[19];
    const float* crm1 = (const float*)d_in[20];
    const float* crv1 = (const float*)d_in[21];
    const float* cW2  = (const float*)d_in[22];
    const float* cb2  = (const float*)d_in[23];
    const float* cg2  = (const float*)d_in[24];
    const float* cbe2 = (const float*)d_in[25];
    const float* crm2 = (const float*)d_in[26];
    const float* crv2 = (const float*)d_in[27];
    const float* cW3  = (const float*)d_in[28];
    const float* cb3  = (const float*)d_in[29];
    float* out = (float*)d_out;

    const int* src = eidx;
    const int* dst = eidx + NE;

    const int EW_QUARTER = NN * HH / 4;   // 6.4M float4 elements

    // init
    k_zero_agg<<<EW_QUARTER / 256, 256>>>();
    int gi = (BG * HH + 255) / 256 > (NN + 255) / 256 ? (BG * HH + 255) / 256
                                                      : (NN + 255) / 256;
    k_init_small<<<gi, 256>>>();
    k_deg<<<(NE + 255) / 256, 256>>>(dst, ew);
    k_cnt<<<(NN + 255) / 256, 256>>>(batch);
    k_dinv<<<(NN + 255) / 256, 256>>>();

    // layer 1
    {
        dim3 grid((NN + 127) / 128, HH / 64);
        k_sgemm<DIN, 0><<<grid, 256>>>(x, W1, NN);
    }
    k_scatter<<<(NE * 32) / 256, 256>>>(src, dst, ew);
    k_post1<<<EW_QUARTER / 256, 256>>>(b1, g1, be1, rm1, rv1);

    // layer 2
    {
        dim3 grid((NN + 127) / 128, HH / 64);
        k_sgemm<HH, 1><<<grid, 256>>>(x /*unused*/, W2, NN);
    }
    k_scatter<<<(NE * 32) / 256, 256>>>(src, dst, ew);
    k_post2<<<EW_QUARTER / 256, 256>>>(b2, g2, be2, rm2, rv2, batch);

    // head
    k_classifier<<<BG, 256>>>(cW1, cb1, cg1, cbe1, crm1, crv1,
                              cW2, cb2, cg2, cbe2, crm2, crv2,
                              cW3, cb3, out, out_size);
}

// round 5
// speedup vs baseline: 1.1543x; 1.1543x over previous
#include <cuda_runtime.h>
#include <cuda_bf16.h>

// Problem constants (fixed by dataset)
#define NN   100000
#define NE   1600000
#define BG   256
#define DIN  128
#define HH   256
#define BN_EPS 1e-5f

// ---------------------------------------------------------------------------
// Scratch (device globals; referenced ONLY inside kernel bodies)
// ---------------------------------------------------------------------------
__device__ float g_h[(size_t)NN * HH];    // GEMM output (h = A@W)
__device__ float g_agg[(size_t)NN * HH];  // scatter accumulator
__device__ float g_act[(size_t)NN * HH];  // activated layer output / residual
__device__ float g_deg[NN];
__device__ float g_dinv[NN];
__device__ float g_pool[BG * HH];
__device__ float g_cnt[BG];

// Vector reduction (no-return atomic add), sm_90+
__device__ __forceinline__ void red_add_v4(float* a, float4 v) {
    asm volatile("red.global.add.v4.f32 [%0], {%1,%2,%3,%4};"
                 :: "l"(a), "f"(v.x), "f"(v.y), "f"(v.z), "f"(v.w) : "memory");
}

__device__ __forceinline__ unsigned tf32_of(float f) {
    unsigned u;
    asm("cvt.rna.tf32.f32 %0, %1;" : "=r"(u) : "f"(f));
    return u;
}

// ---------------------------------------------------------------------------
// Init kernels
// ---------------------------------------------------------------------------
__global__ void k_zero_agg() {
    int i = blockIdx.x * blockDim.x + threadIdx.x;  // NN*HH/4 threads
    ((float4*)g_agg)[i] = make_float4(0.f, 0.f, 0.f, 0.f);
}

__global__ void k_init_small() {
    int i = blockIdx.x * blockDim.x + threadIdx.x;
    if (i < NN) g_deg[i] = 1.0f;          // self-loop weight
    if (i < BG * HH) g_pool[i] = 0.0f;
    if (i < BG) g_cnt[i] = 0.0f;
}

__global__ void k_deg(const int* __restrict__ dst, const float* __restrict__ ew) {
    int e = blockIdx.x * blockDim.x + threadIdx.x;
    if (e < NE) atomicAdd(&g_deg[dst[e]], ew[e]);
}

__global__ void k_cnt(const int* __restrict__ batch) {
    int n = blockIdx.x * blockDim.x + threadIdx.x;
    if (n < NN) atomicAdd(&g_cnt[batch[n]], 1.0f);
}

__global__ void k_dinv() {
    int n = blockIdx.x * blockDim.x + threadIdx.x;
    if (n < NN) g_dinv[n] = rsqrtf(g_deg[n]);
}

// ---------------------------------------------------------------------------
// TF32 tensor-core GEMM: g_h[M x 256] = A[M x K] @ B[K x 256]
// BM=128, BN=128, BK=32. 8 warps: warp grid 2(m) x 4(n), warp tile 64x32.
// mma.sync.aligned.m16n8k8.row.col.f32.tf32.tf32.f32
// ---------------------------------------------------------------------------
template <int K, int USE_ACT>
__global__ __launch_bounds__(256) void k_mma(const float* __restrict__ Aparam,
                                             const float* __restrict__ Bm, int M) {
    const float* A = USE_ACT ? (const float*)g_act : Aparam;
    float* C = g_h;
    const int BM = 128, BN = 128, BK = 32;
    __shared__ float As[BK][BM + 4];   // [k][m], transposed
    __shared__ float Bs[BK][BN + 4];   // [k][n]

    int tid  = threadIdx.x;
    int wid  = tid >> 5, lane = tid & 31;
    int gid  = lane >> 2, tig = lane & 3;     // group-of-4 id / id-in-group
    int wm   = (wid & 1) * 64;                // warp m offset (0/64)
    int wn   = (wid >> 1) * 32;               // warp n offset (0/32/64/96)
    int bm   = blockIdx.x * BM;
    int bn   = blockIdx.y * BN;

    float c[4][4][4];                          // [mfrag][nfrag][c0..c3]
#pragma unroll
    for (int mf = 0; mf < 4; mf++)
#pragma unroll
        for (int nf = 0; nf < 4; nf++)
#pragma unroll
            for (int j = 0; j < 4; j++) c[mf][nf][j] = 0.f;

    for (int k0 = 0; k0 < K; k0 += BK) {
        // --- A tile (128 x 32): 1024 float4, 4 per thread, transpose + cvt ---
#pragma unroll
        for (int p = 0; p < 4; p++) {
            int row  = (tid >> 3) + p * 32;
            int col4 = tid & 7;
            int gm = bm + row;
            float4 v = make_float4(0.f, 0.f, 0.f, 0.f);
            if (gm < M) v = *(const float4*)(A + (size_t)gm * K + k0 + col4 * 4);
            As[col4 * 4 + 0][row] = __uint_as_float(tf32_of(v.x));
            As[col4 * 4 + 1][row] = __uint_as_float(tf32_of(v.y));
            As[col4 * 4 + 2][row] = __uint_as_float(tf32_of(v.z));
            As[col4 * 4 + 3][row] = __uint_as_float(tf32_of(v.w));
        }
        // --- B tile (32 x 128): 1024 float4, 4 per thread ---
#pragma unroll
        for (int p = 0; p < 4; p++) {
            int row  = (tid >> 5) + p * 8;
            int col4 = tid & 31;
            float4 v = *(const float4*)(Bm + (size_t)(k0 + row) * HH + bn + col4 * 4);
            Bs[row][col4 * 4 + 0] = __uint_as_float(tf32_of(v.x));
            Bs[row][col4 * 4 + 1] = __uint_as_float(tf32_of(v.y));
            Bs[row][col4 * 4 + 2] = __uint_as_float(tf32_of(v.z));
            Bs[row][col4 * 4 + 3] = __uint_as_float(tf32_of(v.w));
        }
        __syncthreads();

#pragma unroll
        for (int ks = 0; ks < 4; ks++) {
            int kk = ks * 8;
            unsigned a[4][4], b[4][2];
#pragma unroll
            for (int mf = 0; mf < 4; mf++) {
                int r0 = wm + mf * 16 + gid;
                a[mf][0] = __float_as_uint(As[kk + tig    ][r0    ]);
                a[mf][1] = __float_as_uint(As[kk + tig    ][r0 + 8]);
                a[mf][2] = __float_as_uint(As[kk + tig + 4][r0    ]);
                a[mf][3] = __float_as_uint(As[kk + tig + 4][r0 + 8]);
            }
#pragma unroll
            for (int nf = 0; nf < 4; nf++) {
                int cc = wn + nf * 8 + gid;
                b[nf][0] = __float_as_uint(Bs[kk + tig    ][cc]);
                b[nf][1] = __float_as_uint(Bs[kk + tig + 4][cc]);
            }
#pragma unroll
            for (int mf = 0; mf < 4; mf++)
#pragma unroll
                for (int nf = 0; nf < 4; nf++) {
                    asm volatile(
                        "mma.sync.aligned.m16n8k8.row.col.f32.tf32.tf32.f32 "
                        "{%0,%1,%2,%3}, {%4,%5,%6,%7}, {%8,%9}, {%0,%1,%2,%3};"
                        : "+f"(c[mf][nf][0]), "+f"(c[mf][nf][1]),
                          "+f"(c[mf][nf][2]), "+f"(c[mf][nf][3])
                        : "r"(a[mf][0]), "r"(a[mf][1]), "r"(a[mf][2]), "r"(a[mf][3]),
                          "r"(b[nf][0]), "r"(b[nf][1]));
                }
        }
        __syncthreads();
    }

    // --- epilogue: per frag, rows (gid, gid+8), cols tig*2, tig*2+1 ---
#pragma unroll
    for (int mf = 0; mf < 4; mf++) {
#pragma unroll
        for (int nf = 0; nf < 4; nf++) {
            int r0 = bm + wm + mf * 16 + gid;
            int cc = bn + wn + nf * 8 + tig * 2;
            if (r0 < M)
                *(float2*)(C + (size_t)r0 * HH + cc) =
                    make_float2(c[mf][nf][0], c[mf][nf][1]);
            if (r0 + 8 < M)
                *(float2*)(C + (size_t)(r0 + 8) * HH + cc) =
                    make_float2(c[mf][nf][2], c[mf][nf][3]);
        }
    }
}

// ---------------------------------------------------------------------------
// Edge scatter: agg[dst] += h[src] * (dinv[src]*ew*dinv[dst])
// One warp per edge; 2 float4 per lane, v4 reductions.
// ---------------------------------------------------------------------------
__global__ __launch_bounds__(256) void k_scatter(const int* __restrict__ src,
                                                 const int* __restrict__ dst,
                                                 const float* __restrict__ ew) {
    int e = (blockIdx.x * blockDim.x + threadIdx.x) >> 5;
    if (e >= NE) return;
    int lane = threadIdx.x & 31;
    int s = __ldg(&src[e]);
    int d = __ldg(&dst[e]);
    float norm = __ldg(&g_dinv[s]) * __ldg(&ew[e]) * __ldg(&g_dinv[d]);
    const float4* hs = (const float4*)(g_h + (size_t)s * HH);
    float* ag = g_agg + (size_t)d * HH;
#pragma unroll
    for (int j = 0; j < 2; j++) {
        int idx = lane + j * 32;
        float4 v = __ldg(&hs[idx]);
        v.x *= norm; v.y *= norm; v.z *= norm; v.w *= norm;
        red_add_v4(ag + idx * 4, v);
    }
}

// ---------------------------------------------------------------------------
// Post layer 1: act = relu(bn(agg + h*dinv^2 + b)); re-zero agg for layer 2
// ---------------------------------------------------------------------------
__global__ __launch_bounds__(256) void k_post1(const float* __restrict__ b1,
                                               const float* __restrict__ gm1,
                                               const float* __restrict__ be1,
                                               const float* __restrict__ rm1,
                                               const float* __restrict__ rv1) {
    int i = blockIdx.x * blockDim.x + threadIdx.x;  // over NN*HH/4
    int n = i >> 6;
    int c4 = i & 63;
    float di = g_dinv[n];
    float sc = di * di;
    float4 a = ((const float4*)g_agg)[i];
    float4 h = ((const float4*)g_h)[i];
    float4 bb = ((const float4*)b1)[c4];
    float4 g = ((const float4*)gm1)[c4];
    float4 be = ((const float4*)be1)[c4];
    float4 rm = ((const float4*)rm1)[c4];
    float4 rv = ((const float4*)rv1)[c4];
    float4 v;
    v.x = a.x + h.x * sc + bb.x;
    v.y = a.y + h.y * sc + bb.y;
    v.z = a.z + h.z * sc + bb.z;
    v.w = a.w + h.w * sc + bb.w;
    v.x = fmaxf((v.x - rm.x) * rsqrtf(rv.x + BN_EPS) * g.x + be.x, 0.f);
    v.y = fmaxf((v.y - rm.y) * rsqrtf(rv.y + BN_EPS) * g.y + be.y, 0.f);
    v.z = fmaxf((v.z - rm.z) * rsqrtf(rv.z + BN_EPS) * g.z + be.z, 0.f);
    v.w = fmaxf((v.w - rm.w) * rsqrtf(rv.w + BN_EPS) * g.w + be.w, 0.f);
    ((float4*)g_act)[i] = v;
    ((float4*)g_agg)[i] = make_float4(0.f, 0.f, 0.f, 0.f);
}

// ---------------------------------------------------------------------------
// Post layer 2: v = relu(bn(agg + h*dinv^2 + b)) + residual(act);
// store to act and accumulate into per-graph pool.
// ---------------------------------------------------------------------------
__global__ __launch_bounds__(256) void k_post2(const float* __restrict__ b2,
                                               const float* __restrict__ gm2,
                                               const float* __restrict__ be2,
                                               const float* __restrict__ rm2,
                                               const float* __restrict__ rv2,
                                               const int* __restrict__ batch) {
    int i = blockIdx.x * blockDim.x + threadIdx.x;
    int n = i >> 6;
    int c4 = i & 63;
    float di = g_dinv[n];
    float sc = di * di;
    float4 a = ((const float4*)g_agg)[i];
    float4 h = ((const float4*)g_h)[i];
    float4 bb = ((const float4*)b2)[c4];
    float4 g = ((const float4*)gm2)[c4];
    float4 be = ((const float4*)be2)[c4];
    float4 rm = ((const float4*)rm2)[c4];
    float4 rv = ((const float4*)rv2)[c4];
    float4 res = ((const float4*)g_act)[i];
    float4 v;
    v.x = a.x + h.x * sc + bb.x;
    v.y = a.y + h.y * sc + bb.y;
    v.z = a.z + h.z * sc + bb.z;
    v.w = a.w + h.w * sc + bb.w;
    v.x = fmaxf((v.x - rm.x) * rsqrtf(rv.x + BN_EPS) * g.x + be.x, 0.f) + res.x;
    v.y = fmaxf((v.y - rm.y) * rsqrtf(rv.y + BN_EPS) * g.y + be.y, 0.f) + res.y;
    v.z = fmaxf((v.z - rm.z) * rsqrtf(rv.z + BN_EPS) * g.z + be.z, 0.f) + res.z;
    v.w = fmaxf((v.w - rm.w) * rsqrtf(rv.w + BN_EPS) * g.w + be.w, 0.f) + res.w;
    ((float4*)g_act)[i] = v;
    int b = __ldg(&batch[n]);
    red_add_v4(&g_pool[b * HH + c4 * 4], v);
}

// ---------------------------------------------------------------------------
// Classifier head: one block per graph, 256 threads.
// ---------------------------------------------------------------------------
__global__ __launch_bounds__(256) void k_classifier(
    const float* __restrict__ cW1, const float* __restrict__ cb1,
    const float* __restrict__ cg1, const float* __restrict__ cbe1,
    const float* __restrict__ crm1, const float* __restrict__ crv1,
    const float* __restrict__ cW2, const float* __restrict__ cb2,
    const float* __restrict__ cg2, const float* __restrict__ cbe2,
    const float* __restrict__ crm2, const float* __restrict__ crv2,
    const float* __restrict__ cW3, const float* __restrict__ cb3,
    float* __restrict__ out, int out_size) {
    __shared__ float e[256];
    __shared__ float z1[256];
    __shared__ float z2[128];
    int g = blockIdx.x, t = threadIdx.x;
    float inv = 1.0f / fmaxf(g_cnt[g], 1.0f);
    e[t] = g_pool[g * HH + t] * inv;
    __syncthreads();
    {
        float acc = cb1[t];
#pragma unroll 8
        for (int k = 0; k < 256; k++) acc += e[k] * cW1[k * 256 + t];
        acc = (acc - crm1[t]) * rsqrtf(crv1[t] + BN_EPS) * cg1[t] + cbe1[t];
        z1[t] = fmaxf(acc, 0.f);
    }
    __syncthreads();
    if (t < 128) {
        float acc = cb2[t];
#pragma unroll 8
        for (int k = 0; k < 256; k++) acc += z1[k] * cW2[k * 128 + t];
        acc = (acc - crm2[t]) * rsqrtf(crv2[t] + BN_EPS) * cg2[t] + cbe2[t];
        z2[t] = fmaxf(acc, 0.f);
    }
    __syncthreads();
    float logit = 0.f;
    if (t < 2) {
        logit = cb3[t];
#pragma unroll 8
        for (int k = 0; k < 128; k++) logit += z2[k] * cW3[k * 2 + t];
    }
    if (out_size >= 512 + BG * HH) {
        if (t < 2) out[g * 2 + t] = logit;
        out[512 + g * 256 + t] = e[t];
    } else if (out_size == BG * HH) {
        out[g * 256 + t] = e[t];
    } else {
        if (t < 2 && g * 2 + t < out_size) out[g * 2 + t] = logit;
    }
}

// ---------------------------------------------------------------------------
// Launch
// ---------------------------------------------------------------------------
extern "C" void kernel_launch(void* const* d_in, const int* in_sizes, int n_in,
                              void* d_out, int out_size) {
    const float* x    = (const float*)d_in[0];
    const int*   eidx = (const int*)d_in[1];
    const float* ew   = (const float*)d_in[2];
    const int*   batch= (const int*)d_in[3];
    const float* W1   = (const float*)d_in[4];
    const float* b1   = (const float*)d_in[5];
    const float* g1   = (const float*)d_in[6];
    const float* be1  = (const float*)d_in[7];
    const float* rm1  = (const float*)d_in[8];
    const float* rv1  = (const float*)d_in[9];
    const float* W2   = (const float*)d_in[10];
    const float* b2   = (const float*)d_in[11];
    const float* g2   = (const float*)d_in[12];
    const float* be2  = (const float*)d_in[13];
    const float* rm2  = (const float*)d_in[14];
    const float* rv2  = (const float*)d_in[15];
    const float* cW1  = (const float*)d_in[16];
    const float* cb1  = (const float*)d_in[17];
    const float* cg1  = (const float*)d_in[18];
    const float* cbe1 = (const float*)d_in[19];
    const float* crm1 = (const float*)d_in[20];
    const float* crv1 = (const float*)d_in[21];
    const float* cW2  = (const float*)d_in[22];
    const float* cb2  = (const float*)d_in[23];
    const float* cg2  = (const float*)d_in[24];
    const float* cbe2 = (const float*)d_in[25];
    const float* crm2 = (const float*)d_in[26];
    const float* crv2 = (const float*)d_in[27];
    const float* cW3  = (const float*)d_in[28];
    const float* cb3  = (const float*)d_in[29];
    float* out = (float*)d_out;

    const int* src = eidx;
    const int* dst = eidx + NE;

    const int EW_QUARTER = NN * HH / 4;   // 6.4M float4 elements

    // init
    k_zero_agg<<<EW_QUARTER / 256, 256>>>();
    int gi = (BG * HH + 255) / 256 > (NN + 255) / 256 ? (BG * HH + 255) / 256
                                                      : (NN + 255) / 256;
    k_init_small<<<gi, 256>>>();
    k_deg<<<(NE + 255) / 256, 256>>>(dst, ew);
    k_cnt<<<(NN + 255) / 256, 256>>>(batch);
    k_dinv<<<(NN + 255) / 256, 256>>>();

    // layer 1
    {
        dim3 grid((NN + 127) / 128, HH / 128);
        k_mma<DIN, 0><<<grid, 256>>>(x, W1, NN);
    }
    k_scatter<<<(NE * 32) / 256, 256>>>(src, dst, ew);
    k_post1<<<EW_QUARTER / 256, 256>>>(b1, g1, be1, rm1, rv1);

    // layer 2
    {
        dim3 grid((NN + 127) / 128, HH / 128);
        k_mma<HH, 1><<<grid, 256>>>(x /*unused*/, W2, NN);
    }
    k_scatter<<<(NE * 32) / 256, 256>>>(src, dst, ew);
    k_post2<<<EW_QUARTER / 256, 256>>>(b2, g2, be2, rm2, rv2, batch);

    // head
    k_classifier<<<BG, 256>>>(cW1, cb1, cg1, cbe1, crm1, crv1,
                              cW2, cb2, cg2, cbe2, crm2, crv2,
                              cW3, cb3, out, out_size);
}

// round 6
// speedup vs baseline: 1.9893x; 1.7233x over previous
#include <cuda_runtime.h>
#include <cuda_bf16.h>

// Problem constants (fixed by dataset)
#define NN   100000
#define NE   1600000
#define BG   256
#define DIN  128
#define HH   256
#define BN_EPS 1e-5f

// ---------------------------------------------------------------------------
// Scratch (device globals; referenced ONLY inside kernel bodies)
// ---------------------------------------------------------------------------
__device__ float g_p1[(size_t)NN * DIN];   // aggregated x (layer-1 propagate-first)
__device__ float g_act1[(size_t)NN * HH];  // layer-1 activation / residual
__device__ float g_p2[(size_t)NN * HH];    // aggregated act1
__device__ int   g_esrc[NE];               // CSR: src per edge slot
__device__ float g_enorm[NE];              // CSR: dinv[s]*ew*dinv[d] per edge slot
__device__ int   g_offs[NN + 1];           // CSR row offsets
__device__ int   g_cursor[NN];             // reorder cursors
__device__ int   g_hist[NN];               // in-degree histogram
__device__ float g_deg[NN];
__device__ float g_dinv[NN];
__device__ float g_pool[BG * HH];
__device__ float g_cnt[BG];
__device__ float g_alpha1[HH], g_beta1[HH], g_alpha2[HH], g_beta2[HH];

__device__ __forceinline__ void red_add_v2(float* a, float x, float y) {
    asm volatile("red.global.add.v2.f32 [%0], {%1,%2};"
                 :: "l"(a), "f"(x), "f"(y) : "memory");
}

__device__ __forceinline__ unsigned tf32_of(float f) {
    unsigned u;
    asm("cvt.rna.tf32.f32 %0, %1;" : "=r"(u) : "f"(f));
    return u;
}

// ---------------------------------------------------------------------------
// Init: deg=1 (self loop), hist=0, pool=0, cnt=0
// ---------------------------------------------------------------------------
__global__ void k_init() {
    int i = blockIdx.x * blockDim.x + threadIdx.x;
    if (i < NN) { g_deg[i] = 1.0f; g_hist[i] = 0; }
    if (i < BG * HH) g_pool[i] = 0.0f;
    if (i < BG) g_cnt[i] = 0.0f;
}

// BN constant folding: alpha = g*rsqrt(rv+eps), beta = (b - rm)*alpha + be
__global__ void k_bnprep(const float* __restrict__ b1, const float* __restrict__ g1,
                         const float* __restrict__ be1, const float* __restrict__ rm1,
                         const float* __restrict__ rv1,
                         const float* __restrict__ b2, const float* __restrict__ g2,
                         const float* __restrict__ be2, const float* __restrict__ rm2,
                         const float* __restrict__ rv2) {
    int c = threadIdx.x;
    float a1 = g1[c] * rsqrtf(rv1[c] + BN_EPS);
    g_alpha1[c] = a1;
    g_beta1[c] = (b1[c] - rm1[c]) * a1 + be1[c];
    float a2 = g2[c] * rsqrtf(rv2[c] + BN_EPS);
    g_alpha2[c] = a2;
    g_beta2[c] = (b2[c] - rm2[c]) * a2 + be2[c];
}

__global__ void k_edge_stats(const int* __restrict__ dst, const float* __restrict__ ew) {
    int e = blockIdx.x * blockDim.x + threadIdx.x;
    if (e < NE) {
        int d = dst[e];
        atomicAdd(&g_deg[d], ew[e]);
        atomicAdd(&g_hist[d], 1);
    }
}

__global__ void k_cnt(const int* __restrict__ batch) {
    int n = blockIdx.x * blockDim.x + threadIdx.x;
    if (n < NN) atomicAdd(&g_cnt[batch[n]], 1.0f);
}

__global__ void k_dinv() {
    int n = blockIdx.x * blockDim.x + threadIdx.x;
    if (n < NN) g_dinv[n] = rsqrtf(g_deg[n]);
}

// Single-block exclusive scan of g_hist -> g_offs (+ copy to g_cursor)
__global__ __launch_bounds__(1024) void k_scan() {
    __shared__ int partial[1024];
    const int CH = (NN + 1023) / 1024;  // 98
    int t = threadIdx.x;
    int lo = t * CH, hi = min(lo + CH, NN);
    int sum = 0;
    for (int i = lo; i < hi; i++) sum += g_hist[i];
    partial[t] = sum;
    __syncthreads();
    // Hillis-Steele inclusive scan
    for (int off = 1; off < 1024; off <<= 1) {
        int v = (t >= off) ? partial[t - off] : 0;
        __syncthreads();
        partial[t] += v;
        __syncthreads();
    }
    int base = (t == 0) ? 0 : partial[t - 1];
    for (int i = lo; i < hi; i++) {
        int h = g_hist[i];
        g_offs[i] = base;
        g_cursor[i] = base;
        base += h;
    }
    if (t == 1023) g_offs[NN] = partial[1023];
}

__global__ void k_reorder(const int* __restrict__ src, const int* __restrict__ dst,
                          const float* __restrict__ ew) {
    int e = blockIdx.x * blockDim.x + threadIdx.x;
    if (e >= NE) return;
    int d = dst[e];
    int s = src[e];
    int pos = atomicAdd(&g_cursor[d], 1);
    g_esrc[pos] = s;
    g_enorm[pos] = g_dinv[s] * ew[e] * g_dinv[d];
}

// ---------------------------------------------------------------------------
// Gather-side aggregation: p[n] = sum_{e in in(n)} norm_e * X[src_e] + X[n]*dinv^2
// Warp per node. COLS/128 float4 per lane. SRC: 0 -> x param -> g_p1,
//                                             1 -> g_act1  -> g_p2
// ---------------------------------------------------------------------------
template <int COLS, int SRC>
__global__ __launch_bounds__(256) void k_gather(const float* __restrict__ xin) {
    int n = (blockIdx.x * blockDim.x + threadIdx.x) >> 5;
    if (n >= NN) return;
    int lane = threadIdx.x & 31;
    const float* X = SRC ? (const float*)g_act1 : xin;
    float* P = SRC ? g_p2 : g_p1;
    const int NV = COLS / 128;

    float di = g_dinv[n];
    float sc = di * di;
    const float4* xn = (const float4*)(X + (size_t)n * COLS);
    float4 acc[NV];
#pragma unroll
    for (int j = 0; j < NV; j++) {
        float4 v = __ldg(&xn[lane + j * 32]);
        acc[j] = make_float4(v.x * sc, v.y * sc, v.z * sc, v.w * sc);
    }
    int beg = g_offs[n], end = g_offs[n + 1];
    for (int e = beg; e < end; e++) {
        int s = __ldg(&g_esrc[e]);
        float w = __ldg(&g_enorm[e]);
        const float4* xs = (const float4*)(X + (size_t)s * COLS);
#pragma unroll
        for (int j = 0; j < NV; j++) {
            float4 v = __ldg(&xs[lane + j * 32]);
            acc[j].x += w * v.x; acc[j].y += w * v.y;
            acc[j].z += w * v.z; acc[j].w += w * v.w;
        }
    }
    float4* pn = (float4*)(P + (size_t)n * COLS);
#pragma unroll
    for (int j = 0; j < NV; j++) pn[lane + j * 32] = acc[j];
}

// ---------------------------------------------------------------------------
// TF32 tensor-core GEMM with fused epilogue.
// LAYER=1: act1 = relu(alpha1*(p1@W1) + beta1)
// LAYER=2: v = relu(alpha2*(p2@W2) + beta2) + act1;  red v -> pool[batch]
// BM=128, BN=128, BK=32, 8 warps (2m x 4n), warp tile 64x32, m16n8k8 tf32.
// ---------------------------------------------------------------------------
template <int K, int LAYER>
__global__ __launch_bounds__(256) void k_mma(const float* __restrict__ Bm,
                                             const int* __restrict__ batch, int M) {
    const float* A = (LAYER == 1) ? g_p1 : g_p2;
    const int BM = 128, BN = 128, BK = 32;
    __shared__ float As[BK][BM + 4];
    __shared__ float Bs[BK][BN + 4];

    int tid  = threadIdx.x;
    int wid  = tid >> 5, lane = tid & 31;
    int gid  = lane >> 2, tig = lane & 3;
    int wm   = (wid & 1) * 64;
    int wn   = (wid >> 1) * 32;
    int bm   = blockIdx.x * BM;
    int bn   = blockIdx.y * BN;

    float c[4][4][4];
#pragma unroll
    for (int mf = 0; mf < 4; mf++)
#pragma unroll
        for (int nf = 0; nf < 4; nf++)
#pragma unroll
            for (int j = 0; j < 4; j++) c[mf][nf][j] = 0.f;

    for (int k0 = 0; k0 < K; k0 += BK) {
#pragma unroll
        for (int p = 0; p < 4; p++) {
            int row  = (tid >> 3) + p * 32;
            int col4 = tid & 7;
            int gm = bm + row;
            float4 v = make_float4(0.f, 0.f, 0.f, 0.f);
            if (gm < M) v = *(const float4*)(A + (size_t)gm * K + k0 + col4 * 4);
            As[col4 * 4 + 0][row] = __uint_as_float(tf32_of(v.x));
            As[col4 * 4 + 1][row] = __uint_as_float(tf32_of(v.y));
            As[col4 * 4 + 2][row] = __uint_as_float(tf32_of(v.z));
            As[col4 * 4 + 3][row] = __uint_as_float(tf32_of(v.w));
        }
#pragma unroll
        for (int p = 0; p < 4; p++) {
            int row  = (tid >> 5) + p * 8;
            int col4 = tid & 31;
            float4 v = *(const float4*)(Bm + (size_t)(k0 + row) * HH + bn + col4 * 4);
            Bs[row][col4 * 4 + 0] = __uint_as_float(tf32_of(v.x));
            Bs[row][col4 * 4 + 1] = __uint_as_float(tf32_of(v.y));
            Bs[row][col4 * 4 + 2] = __uint_as_float(tf32_of(v.z));
            Bs[row][col4 * 4 + 3] = __uint_as_float(tf32_of(v.w));
        }
        __syncthreads();

#pragma unroll
        for (int ks = 0; ks < 4; ks++) {
            int kk = ks * 8;
            unsigned a[4][4], b[4][2];
#pragma unroll
            for (int mf = 0; mf < 4; mf++) {
                int r0 = wm + mf * 16 + gid;
                a[mf][0] = __float_as_uint(As[kk + tig    ][r0    ]);
                a[mf][1] = __float_as_uint(As[kk + tig    ][r0 + 8]);
                a[mf][2] = __float_as_uint(As[kk + tig + 4][r0    ]);
                a[mf][3] = __float_as_uint(As[kk + tig + 4][r0 + 8]);
            }
#pragma unroll
            for (int nf = 0; nf < 4; nf++) {
                int cc = wn + nf * 8 + gid;
                b[nf][0] = __float_as_uint(Bs[kk + tig    ][cc]);
                b[nf][1] = __float_as_uint(Bs[kk + tig + 4][cc]);
            }
#pragma unroll
            for (int mf = 0; mf < 4; mf++)
#pragma unroll
                for (int nf = 0; nf < 4; nf++) {
                    asm volatile(
                        "mma.sync.aligned.m16n8k8.row.col.f32.tf32.tf32.f32 "
                        "{%0,%1,%2,%3}, {%4,%5,%6,%7}, {%8,%9}, {%0,%1,%2,%3};"
                        : "+f"(c[mf][nf][0]), "+f"(c[mf][nf][1]),
                          "+f"(c[mf][nf][2]), "+f"(c[mf][nf][3])
                        : "r"(a[mf][0]), "r"(a[mf][1]), "r"(a[mf][2]), "r"(a[mf][3]),
                          "r"(b[nf][0]), "r"(b[nf][1]));
                }
        }
        __syncthreads();
    }

    // --- fused epilogue ---
#pragma unroll
    for (int nf = 0; nf < 4; nf++) {
        int cc = bn + wn + nf * 8 + tig * 2;
        float a0, a1, bb0, bb1;
        if (LAYER == 1) {
            a0 = g_alpha1[cc];     a1 = g_alpha1[cc + 1];
            bb0 = g_beta1[cc];     bb1 = g_beta1[cc + 1];
        } else {
            a0 = g_alpha2[cc];     a1 = g_alpha2[cc + 1];
            bb0 = g_beta2[cc];     bb1 = g_beta2[cc + 1];
        }
#pragma unroll
        for (int mf = 0; mf < 4; mf++) {
            int r0 = bm + wm + mf * 16 + gid;
#pragma unroll
            for (int half = 0; half < 2; half++) {
                int r = r0 + half * 8;
                if (r >= M) continue;
                float v0 = fmaxf(a0 * c[mf][nf][half * 2    ] + bb0, 0.f);
                float v1 = fmaxf(a1 * c[mf][nf][half * 2 + 1] + bb1, 0.f);
                if (LAYER == 1) {
                    *(float2*)(g_act1 + (size_t)r * HH + cc) = make_float2(v0, v1);
                } else {
                    float2 res = *(const float2*)(g_act1 + (size_t)r * HH + cc);
                    v0 += res.x; v1 += res.y;
                    int bgi = __ldg(&batch[r]);
                    red_add_v2(&g_pool[bgi * HH + cc], v0, v1);
                }
            }
        }
    }
}

// ---------------------------------------------------------------------------
// Classifier head: one block per graph, 256 threads.
// ---------------------------------------------------------------------------
__global__ __launch_bounds__(256) void k_classifier(
    const float* __restrict__ cW1, const float* __restrict__ cb1,
    const float* __restrict__ cg1, const float* __restrict__ cbe1,
    const float* __restrict__ crm1, const float* __restrict__ crv1,
    const float* __restrict__ cW2, const float* __restrict__ cb2,
    const float* __restrict__ cg2, const float* __restrict__ cbe2,
    const float* __restrict__ crm2, const float* __restrict__ crv2,
    const float* __restrict__ cW3, const float* __restrict__ cb3,
    float* __restrict__ out, int out_size) {
    __shared__ float e[256];
    __shared__ float z1[256];
    __shared__ float z2[128];
    int g = blockIdx.x, t = threadIdx.x;
    float inv = 1.0f / fmaxf(g_cnt[g], 1.0f);
    e[t] = g_pool[g * HH + t] * inv;
    __syncthreads();
    {
        float acc = cb1[t];
#pragma unroll 8
        for (int k = 0; k < 256; k++) acc += e[k] * cW1[k * 256 + t];
        acc = (acc - crm1[t]) * rsqrtf(crv1[t] + BN_EPS) * cg1[t] + cbe1[t];
        z1[t] = fmaxf(acc, 0.f);
    }
    __syncthreads();
    if (t < 128) {
        float acc = cb2[t];
#pragma unroll 8
        for (int k = 0; k < 256; k++) acc += z1[k] * cW2[k * 128 + t];
        acc = (acc - crm2[t]) * rsqrtf(crv2[t] + BN_EPS) * cg2[t] + cbe2[t];
        z2[t] = fmaxf(acc, 0.f);
    }
    __syncthreads();
    float logit = 0.f;
    if (t < 2) {
        logit = cb3[t];
#pragma unroll 8
        for (int k = 0; k < 128; k++) logit += z2[k] * cW3[k * 2 + t];
    }
    if (out_size >= 512 + BG * HH) {
        if (t < 2) out[g * 2 + t] = logit;
        out[512 + g * 256 + t] = e[t];
    } else if (out_size == BG * HH) {
        out[g * 256 + t] = e[t];
    } else {
        if (t < 2 && g * 2 + t < out_size) out[g * 2 + t] = logit;
    }
}

// ---------------------------------------------------------------------------
// Launch
// ---------------------------------------------------------------------------
extern "C" void kernel_launch(void* const* d_in, const int* in_sizes, int n_in,
                              void* d_out, int out_size) {
    const float* x    = (const float*)d_in[0];
    const int*   eidx = (const int*)d_in[1];
    const float* ew   = (const float*)d_in[2];
    const int*   batch= (const int*)d_in[3];
    const float* W1   = (const float*)d_in[4];
    const float* b1   = (const float*)d_in[5];
    const float* g1   = (const float*)d_in[6];
    const float* be1  = (const float*)d_in[7];
    const float* rm1  = (const float*)d_in[8];
    const float* rv1  = (const float*)d_in[9];
    const float* W2   = (const float*)d_in[10];
    const float* b2   = (const float*)d_in[11];
    const float* g2   = (const float*)d_in[12];
    const float* be2  = (const float*)d_in[13];
    const float* rm2  = (const float*)d_in[14];
    const float* rv2  = (const float*)d_in[15];
    const float* cW1  = (const float*)d_in[16];
    const float* cb1  = (const float*)d_in[17];
    const float* cg1  = (const float*)d_in[18];
    const float* cbe1 = (const float*)d_in[19];
    const float* crm1 = (const float*)d_in[20];
    const float* crv1 = (const float*)d_in[21];
    const float* cW2  = (const float*)d_in[22];
    const float* cb2  = (const float*)d_in[23];
    const float* cg2  = (const float*)d_in[24];
    const float* cbe2 = (const float*)d_in[25];
    const float* crm2 = (const float*)d_in[26];
    const float* crv2 = (const float*)d_in[27];
    const float* cW3  = (const float*)d_in[28];
    const float* cb3  = (const float*)d_in[29];
    float* out = (float*)d_out;

    const int* src = eidx;
    const int* dst = eidx + NE;

    // --- init + CSR build ---
    k_init<<<(NN + 255) / 256, 256>>>();
    k_bnprep<<<1, 256>>>(b1, g1, be1, rm1, rv1, b2, g2, be2, rm2, rv2);
    k_edge_stats<<<(NE + 255) / 256, 256>>>(dst, ew);
    k_cnt<<<(NN + 255) / 256, 256>>>(batch);
    k_dinv<<<(NN + 255) / 256, 256>>>();
    k_scan<<<1, 1024>>>();
    k_reorder<<<(NE + 255) / 256, 256>>>(src, dst, ew);

    // --- layer 1: propagate x (128 cols) then transform+BN+ReLU fused ---
    k_gather<DIN, 0><<<(NN * 32 + 255) / 256, 256>>>(x);
    {
        dim3 grid((NN + 127) / 128, HH / 128);
        k_mma<DIN, 1><<<grid, 256>>>(W1, batch, NN);
    }

    // --- layer 2: propagate act1 (256 cols) then transform+BN+ReLU+residual+pool ---
    k_gather<HH, 1><<<(NN * 32 + 255) / 256, 256>>>(x /*unused*/);
    {
        dim3 grid((NN + 127) / 128, HH / 128);
        k_mma<HH, 2><<<grid, 256>>>(W2, batch, NN);
    }

    // --- head ---
    k_classifier<<<BG, 256>>>(cW1, cb1, cg1, cbe1, crm1, crv1,
                              cW2, cb2, cg2, cbe2, crm2, crv2,
                              cW3, cb3, out, out_size);
}